// round 3
// baseline (speedup 1.0000x reference)
#include <cuda_runtime.h>

// DifferentiableTTFSEncoder: first-fire one-hot over T=64 steps.
// out[b, t, n] = 1.0 at the first t where mem = fma(mem, d, c*(1-d)) >= 1
// (c = x[b,n]*sens[n]); 0 elsewhere. Exact fp32 recurrence (no reset needed:
// output depends only on the FIRST crossing, before which no reset occurs).
//
// R3: R1 structure (float4 STG, block=256, 4 lanes/thread) + T split into
// 4 chunks of 16 steps per block (grid.y=4) to kill the ~15% wave-quantization
// tail (2048 indivisible blocks over 592 SM slots = 3.46 waves -> makespan 4).

#define B_DIM 2048
#define N_DIM 1024
#define T_DIM 64
#define NQ    (N_DIM / 4)   // float4 groups per row = 256
#define TCH   16            // t-steps per block chunk

__global__ void __launch_bounds__(256)
ttfs_kernel(const float* __restrict__ x,
            const float* __restrict__ sens,
            float* __restrict__ out)
{
    const int b  = blockIdx.x;      // batch row
    const int nq = threadIdx.x;     // float4 group within row
    const int t0 = blockIdx.y * TCH;

    // Inputs (coalesced float4)
    const float4 xv = reinterpret_cast<const float4*>(x)[b * NQ + nq];
    const float4 sv = reinterpret_cast<const float4*>(sens)[nq];

    const float d   = 0.60653065971263342360f;  // exp(-0.5), fp32-rounded
    const float omd = 1.0f - d;

    const float cc0 = xv.x * sv.x * omd;
    const float cc1 = xv.y * sv.y * omd;
    const float cc2 = xv.z * sv.z * omd;
    const float cc3 = xv.w * sv.w * omd;

    float m0 = 0.0f, m1 = 0.0f, m2 = 0.0f, m3 = 0.0f;
    bool  f0 = false, f1 = false, f2 = false, f3 = false;

    // Warm-up: advance recurrence to t0 without storing (exact same fp32 ops)
    #pragma unroll 16
    for (int t = 0; t < t0; ++t) {
        m0 = fmaf(m0, d, cc0);
        m1 = fmaf(m1, d, cc1);
        m2 = fmaf(m2, d, cc2);
        m3 = fmaf(m3, d, cc3);
        f0 = f0 || (m0 >= 1.0f);
        f1 = f1 || (m1 >= 1.0f);
        f2 = f2 || (m2 >= 1.0f);
        f3 = f3 || (m3 >= 1.0f);
    }

    // Output base: out[b, t, n], n = nq*4; per-t stride = NQ float4s (4 KB)
    float4* op = reinterpret_cast<float4*>(out)
               + (size_t)b * (size_t)T_DIM * NQ + (size_t)t0 * NQ + nq;

    #pragma unroll
    for (int t = 0; t < TCH; ++t) {
        m0 = fmaf(m0, d, cc0);
        m1 = fmaf(m1, d, cc1);
        m2 = fmaf(m2, d, cc2);
        m3 = fmaf(m3, d, cc3);

        const bool s0 = (m0 >= 1.0f);
        const bool s1 = (m1 >= 1.0f);
        const bool s2 = (m2 >= 1.0f);
        const bool s3 = (m3 >= 1.0f);

        float4 v;
        v.x = (s0 && !f0) ? 1.0f : 0.0f;
        v.y = (s1 && !f1) ? 1.0f : 0.0f;
        v.z = (s2 && !f2) ? 1.0f : 0.0f;
        v.w = (s3 && !f3) ? 1.0f : 0.0f;

        f0 = f0 || s0;
        f1 = f1 || s1;
        f2 = f2 || s2;
        f3 = f3 || s3;

        op[(size_t)t * NQ] = v;
    }
}

extern "C" void kernel_launch(void* const* d_in, const int* in_sizes, int n_in,
                              void* d_out, int out_size)
{
    const float* x    = (const float*)d_in[0];   // [2048, 1024] f32
    const float* sens = (const float*)d_in[1];   // [1024] f32
    float* out        = (float*)d_out;           // [2048, 64, 1024] f32

    dim3 grid(B_DIM, T_DIM / TCH, 1);            // 2048 x 4
    ttfs_kernel<<<grid, 256>>>(x, sens, out);
}

// round 4
// speedup vs baseline: 1.1627x; 1.1627x over previous
#include <cuda_runtime.h>

// DifferentiableTTFSEncoder: first-fire one-hot over T=64 steps.
// Output is sparse: per (b,n) at most ONE 1.0 (at the first t where the
// exact-fp32 recurrence m = fmaf(m, d, c*(1-d)) crosses 1.0), zeros elsewhere.
//
// R4: decouple stores from compute. Phase 1 streams 64 independent zero
// STG.128 (pure store drain, immediate offsets). Phase 2 runs the bit-exact
// recurrence to find the fire step. Phase 3 overwrites <=4 scalar 1.0s.
// Same-thread same-address stores are program-ordered, so overwrite is safe.

#define B_DIM 2048
#define N_DIM 1024
#define T_DIM 64
#define NQ    (N_DIM / 4)   // float4 groups per row = 256

__global__ void __launch_bounds__(256)
ttfs_kernel(const float* __restrict__ x,
            const float* __restrict__ sens,
            float* __restrict__ out)
{
    const int gid = blockIdx.x * blockDim.x + threadIdx.x;  // over B*N/4
    const int b  = gid >> 8;        // / NQ
    const int nq = gid & (NQ - 1);  // % NQ

    // ── Phase 1: blast zeros — 64 independent wide stores, no data deps ──
    float4* op = reinterpret_cast<float4*>(out)
               + (size_t)b * (size_t)T_DIM * NQ + nq;
    const float4 z4 = make_float4(0.0f, 0.0f, 0.0f, 0.0f);
    #pragma unroll
    for (int t = 0; t < T_DIM; ++t) {
        op[(size_t)t * NQ] = z4;
    }

    // ── Phase 2: bit-exact recurrence, find first-fire step per lane ──
    const float4 xv = reinterpret_cast<const float4*>(x)[gid];
    const float4 sv = reinterpret_cast<const float4*>(sens)[nq];

    const float d   = 0.60653065971263342360f;  // exp(-0.5), fp32-rounded
    const float omd = 1.0f - d;

    const float cc0 = xv.x * sv.x * omd;
    const float cc1 = xv.y * sv.y * omd;
    const float cc2 = xv.z * sv.z * omd;
    const float cc3 = xv.w * sv.w * omd;

    float m0 = 0.0f, m1 = 0.0f, m2 = 0.0f, m3 = 0.0f;
    int tx0 = T_DIM, tx1 = T_DIM, tx2 = T_DIM, tx3 = T_DIM;

    #pragma unroll
    for (int t = 0; t < T_DIM; ++t) {
        m0 = fmaf(m0, d, cc0);
        m1 = fmaf(m1, d, cc1);
        m2 = fmaf(m2, d, cc2);
        m3 = fmaf(m3, d, cc3);
        if (tx0 == T_DIM && m0 >= 1.0f) tx0 = t;
        if (tx1 == T_DIM && m1 >= 1.0f) tx1 = t;
        if (tx2 == T_DIM && m2 >= 1.0f) tx2 = t;
        if (tx3 == T_DIM && m3 >= 1.0f) tx3 = t;
    }

    // ── Phase 3: overwrite the (at most 4) fire positions with 1.0 ──
    float* ob = out + (size_t)b * (size_t)(T_DIM * N_DIM) + (size_t)(nq * 4);
    if (tx0 < T_DIM) ob[(size_t)tx0 * N_DIM + 0] = 1.0f;
    if (tx1 < T_DIM) ob[(size_t)tx1 * N_DIM + 1] = 1.0f;
    if (tx2 < T_DIM) ob[(size_t)tx2 * N_DIM + 2] = 1.0f;
    if (tx3 < T_DIM) ob[(size_t)tx3 * N_DIM + 3] = 1.0f;
}

extern "C" void kernel_launch(void* const* d_in, const int* in_sizes, int n_in,
                              void* d_out, int out_size)
{
    const float* x    = (const float*)d_in[0];   // [2048, 1024] f32
    const float* sens = (const float*)d_in[1];   // [1024] f32
    float* out        = (float*)d_out;           // [2048, 64, 1024] f32

    const int total_threads = (B_DIM * N_DIM) / 4;  // 524288
    const int block = 256;
    const int grid  = total_threads / block;        // 2048

    ttfs_kernel<<<grid, block>>>(x, sens, out);
}

// round 5
// speedup vs baseline: 1.2685x; 1.0910x over previous
#include <cuda_runtime.h>

// DifferentiableTTFSEncoder: first-fire one-hot over T=64 steps.
// out[b, t, n] = 1.0f at the first t where the exact-fp32 LIF recurrence
// mem = fmaf(mem, d, c*(1-d)), c = x[b,n]*sens[n], crosses 1.0; else 0.
//
// R5: identical interleaved compute+store structure to R1 (best pacing).
// Only change: occupancy shaped to 7 blocks/SM (launch_bounds regs<=32 +
// 30KB unused dynamic smem) so grid=2048 runs as 2 nearly-full waves
// (2048/1036 = 1.98) instead of 3 ragged ones (2048/888 = 2.31, 31%-full
// tail wave == the measured 76.7% DRAM ceiling).

#define B_DIM 2048
#define N_DIM 1024
#define T_DIM 64
#define NQ    (N_DIM / 4)   // float4 groups per row = 256

#define SMEM_PAD_BYTES (30 * 1024)   // occupancy shaper: 228KB/30KB -> 7 blocks/SM

__global__ void __launch_bounds__(256, 8)
ttfs_kernel(const float* __restrict__ x,
            const float* __restrict__ sens,
            float* __restrict__ out)
{
    extern __shared__ float smem_pad[];  // unused; reserves smem for occupancy
    (void)smem_pad;

    const int gid = blockIdx.x * blockDim.x + threadIdx.x;  // over B*N/4
    const int b  = gid >> 8;        // / NQ (NQ = 256)
    const int nq = gid & (NQ - 1);  // % NQ

    // Inputs (coalesced float4)
    const float4 xv = reinterpret_cast<const float4*>(x)[gid];
    const float4 sv = reinterpret_cast<const float4*>(sens)[nq];

    const float d   = 0.60653065971263342360f;  // exp(-0.5), fp32-rounded
    const float omd = 1.0f - d;

    // Per-element constant drive c*(1-d)
    const float cc0 = xv.x * sv.x * omd;
    const float cc1 = xv.y * sv.y * omd;
    const float cc2 = xv.z * sv.z * omd;
    const float cc3 = xv.w * sv.w * omd;

    float m0 = 0.0f, m1 = 0.0f, m2 = 0.0f, m3 = 0.0f;
    bool  f0 = false, f1 = false, f2 = false, f3 = false;

    // Output base: out[b, t, n] with n = nq*4; stride per t is N_DIM floats
    float4* op = reinterpret_cast<float4*>(out)
               + (size_t)b * (size_t)T_DIM * NQ + nq;

    #pragma unroll
    for (int t = 0; t < T_DIM; ++t) {
        m0 = fmaf(m0, d, cc0);
        m1 = fmaf(m1, d, cc1);
        m2 = fmaf(m2, d, cc2);
        m3 = fmaf(m3, d, cc3);

        const bool s0 = (m0 >= 1.0f);
        const bool s1 = (m1 >= 1.0f);
        const bool s2 = (m2 >= 1.0f);
        const bool s3 = (m3 >= 1.0f);

        float4 v;
        v.x = (s0 && !f0) ? 1.0f : 0.0f;
        v.y = (s1 && !f1) ? 1.0f : 0.0f;
        v.z = (s2 && !f2) ? 1.0f : 0.0f;
        v.w = (s3 && !f3) ? 1.0f : 0.0f;

        f0 = f0 || s0;
        f1 = f1 || s1;
        f2 = f2 || s2;
        f3 = f3 || s3;

        op[(size_t)t * NQ] = v;
    }
}

extern "C" void kernel_launch(void* const* d_in, const int* in_sizes, int n_in,
                              void* d_out, int out_size)
{
    const float* x    = (const float*)d_in[0];   // [2048, 1024] f32
    const float* sens = (const float*)d_in[1];   // [1024] f32
    float* out        = (float*)d_out;           // [2048, 64, 1024] f32

    const int total_threads = (B_DIM * N_DIM) / 4;  // 524288
    const int block = 256;
    const int grid  = total_threads / block;        // 2048

    ttfs_kernel<<<grid, block, SMEM_PAD_BYTES>>>(x, sens, out);
}